// round 7
// baseline (speedup 1.0000x reference)
#include <cuda_runtime.h>
#include <cuda_bf16.h>

// TD loss backward recurrence, T=256, B=65536.
// R7: scalar (1 col/thread) -> 2048 warps (~13.8/SM, 2x R4-R6) for smoother
// aggregate load issue, with double-buffered BATCH=8 (56 LDG.32 in flight
// per warp ~= M_max) at ~150 regs. R5/R6 showed per-warp MLP beyond R4 is
// useless at 7 warps/SM; this doubles warp concurrency at equal in-flight.

#define TD_T 256
#define TD_GAMMA 0.99f
#define BATCH 8
#define NBATCH 31   // batches cover t = 247 .. 0 (peel handles 254..248)

struct Buf {
    float d[BATCH], r[BATCH], tv[BATCH], vl[BATCH];
    int   st[BATCH], rb[BATCH], tn[BATCH];
};

__device__ __forceinline__ void load_batch(
    Buf& bf, int j, int b, int B,
    const float* __restrict__ rw, const float* __restrict__ dc,
    const float* __restrict__ vl, const float* __restrict__ tv,
    const int* __restrict__ st, const int* __restrict__ rb,
    const int* __restrict__ tn)
{
    const int tb_hi = 247 - BATCH * j;
    #pragma unroll
    for (int k = 0; k < BATCH; ++k) {
        const int t  = tb_hi - k;
        const int i  = t * B + b;
        const int i1 = i + B;
        bf.d[k]  = __ldcs(&dc[i1]);
        bf.r[k]  = __ldcs(&rw[i1]);
        bf.st[k] = __ldcs(&st[i]);
        bf.rb[k] = __ldcs(&rb[i]);
        bf.tn[k] = __ldcs(&tn[i]);
        bf.tv[k] = __ldcs(&tv[i]);
        bf.vl[k] = __ldcs(&vl[i]);
    }
}

__device__ __forceinline__ void compute_batch(
    const Buf& bf, int j, int b, int B, float& acc,
    float* __restrict__ out)
{
    const int tb_hi = 247 - BATCH * j;
    #pragma unroll
    for (int k = 0; k < BATCH; ++k) {
        const int t = tb_hi - k;
        const bool l = (bf.st[k] == 2) ||
                       ((t != 0) && ((bf.rb[k] | bf.tn[k]) != 0));
        const float ret = fmaf(acc, bf.d[k] * TD_GAMMA, bf.r[k]);
        acc = l ? bf.tv[k] : ret;
        const float diff = ret - bf.vl[k];
        __stcs(&out[t * B + b], diff * diff);
    }
}

__global__ void __launch_bounds__(64, 1) td_loss_kernel(
    const float* __restrict__ reward,
    const float* __restrict__ discount,
    const float* __restrict__ value,
    const float* __restrict__ target_value,
    const int*   __restrict__ step_type,
    const int*   __restrict__ rollout_b,
    const int*   __restrict__ train_b,
    float*       __restrict__ out,
    int B)
{
    const int b = blockIdx.x * blockDim.x + threadIdx.x;
    if (b >= B) return;

    const int base = (TD_T - 1) * B + b;
    float acc = __ldcs(&target_value[base]);
    __stcs(&out[base], 0.0f);

    // Peel t = 254 .. 248 (7 steps, all t > 0).
    #pragma unroll
    for (int t = TD_T - 2; t >= 248; --t) {
        const int i  = t * B + b;
        const int i1 = i + B;
        const float d  = __ldcs(&discount[i1]);
        const float r  = __ldcs(&reward[i1]);
        const int   st = __ldcs(&step_type[i]);
        const int   rb = __ldcs(&rollout_b[i]);
        const int   tn = __ldcs(&train_b[i]);
        const float tv = __ldcs(&target_value[i]);
        const float vl = __ldcs(&value[i]);
        const bool l = (st == 2) || ((rb | tn) != 0);
        const float ret = fmaf(acc, d * TD_GAMMA, r);
        acc = l ? tv : ret;
        const float diff = ret - vl;
        __stcs(&out[i], diff * diff);
    }

    // Double-buffered pipeline over 31 batches (odd): unroll by 2 + epilogue.
    Buf bufA, bufB;
    load_batch(bufA, 0, b, B, reward, discount, value, target_value,
               step_type, rollout_b, train_b);

    #pragma unroll 1
    for (int j = 0; j + 1 < NBATCH; j += 2) {
        load_batch(bufB, j + 1, b, B, reward, discount, value, target_value,
                   step_type, rollout_b, train_b);
        compute_batch(bufA, j, b, B, acc, out);
        if (j + 2 < NBATCH)
            load_batch(bufA, j + 2, b, B, reward, discount, value, target_value,
                       step_type, rollout_b, train_b);
        compute_batch(bufB, j + 1, b, B, acc, out);
    }
    // Final batch (j = 30) already resident in bufA.
    compute_batch(bufA, NBATCH - 1, b, B, acc, out);
}

extern "C" void kernel_launch(void* const* d_in, const int* in_sizes, int n_in,
                              void* d_out, int out_size)
{
    const float* reward       = (const float*)d_in[0];
    const float* discount     = (const float*)d_in[1];
    const float* value        = (const float*)d_in[2];
    const float* target_value = (const float*)d_in[3];
    const int*   step_type    = (const int*)d_in[4];
    const int*   rollout_b    = (const int*)d_in[5];
    const int*   train_b      = (const int*)d_in[6];
    float*       out          = (float*)d_out;

    const int B = in_sizes[0] / TD_T;

    const int threads = 64;
    const int blocks  = (B + threads - 1) / threads;
    td_loss_kernel<<<blocks, threads>>>(reward, discount, value, target_value,
                                        step_type, rollout_b, train_b, out, B);
}

// round 8
// speedup vs baseline: 1.3181x; 1.3181x over previous
#include <cuda_runtime.h>
#include <cuda_bf16.h>

// TD loss backward recurrence, T=256, B=65536.
// R8: R4's winning structure (float2, double buffer, 64-thread blocks) with
// BATCH=3 to cut register pressure 160 -> ~130. Cross-round evidence:
// LDG.64 width is necessary (LDG.32 rounds: 39-62% DRAM), and regs above
// ~160 monotonically hurt (160/200/254 -> 78.2/80.4/79.7+ us kernel).
// 255 = 3*85 -> no peel loop; smaller, more frequent load bursts.

#define TD_T 256
#define TD_GAMMA 0.99f
#define BATCH 3
#define NBATCH 85   // batches cover t = 254 .. 0

struct Buf {
    float2 d[BATCH], r[BATCH], tv[BATCH], vl[BATCH];
    int2   st[BATCH], rb[BATCH], tn[BATCH];
};

__device__ __forceinline__ void load_batch(
    Buf& bf, int j, int p, int P,
    const float2* __restrict__ rw2, const float2* __restrict__ dc2,
    const float2* __restrict__ vl2, const float2* __restrict__ tv2,
    const int2* __restrict__ st2, const int2* __restrict__ rb2,
    const int2* __restrict__ tb2)
{
    const int tb_hi = (TD_T - 2) - BATCH * j;   // 254, 251, ..., 2
    #pragma unroll
    for (int k = 0; k < BATCH; ++k) {
        const int t  = tb_hi - k;
        const int i  = t * P + p;
        const int i1 = i + P;
        bf.d[k]  = __ldcs(&dc2[i1]);
        bf.r[k]  = __ldcs(&rw2[i1]);
        bf.st[k] = __ldcs(&st2[i]);
        bf.rb[k] = __ldcs(&rb2[i]);
        bf.tn[k] = __ldcs(&tb2[i]);
        bf.tv[k] = __ldcs(&tv2[i]);
        bf.vl[k] = __ldcs(&vl2[i]);
    }
}

__device__ __forceinline__ void compute_batch(
    const Buf& bf, int j, int p, int P, float2& acc,
    float2* __restrict__ ot2)
{
    const int tb_hi = (TD_T - 2) - BATCH * j;
    #pragma unroll
    for (int k = 0; k < BATCH; ++k) {
        const int t = tb_hi - k;
        const bool nz = (t != 0);
        const bool lx = (bf.st[k].x == 2) || (nz && ((bf.rb[k].x | bf.tn[k].x) != 0));
        const bool ly = (bf.st[k].y == 2) || (nz && ((bf.rb[k].y | bf.tn[k].y) != 0));
        const float retx = fmaf(acc.x, bf.d[k].x * TD_GAMMA, bf.r[k].x);
        const float rety = fmaf(acc.y, bf.d[k].y * TD_GAMMA, bf.r[k].y);
        acc.x = lx ? bf.tv[k].x : retx;
        acc.y = ly ? bf.tv[k].y : rety;
        const float dx = retx - bf.vl[k].x;
        const float dy = rety - bf.vl[k].y;
        __stcs(&ot2[t * P + p], make_float2(dx * dx, dy * dy));
    }
}

__global__ void __launch_bounds__(64, 1) td_loss_kernel(
    const float* __restrict__ reward,
    const float* __restrict__ discount,
    const float* __restrict__ value,
    const float* __restrict__ target_value,
    const int*   __restrict__ step_type,
    const int*   __restrict__ rollout_b,
    const int*   __restrict__ train_b,
    float*       __restrict__ out,
    int B)
{
    const int p = blockIdx.x * blockDim.x + threadIdx.x;
    const int P = B >> 1;
    if (p >= P) return;

    const float2* __restrict__ rw2 = (const float2*)reward;
    const float2* __restrict__ dc2 = (const float2*)discount;
    const float2* __restrict__ vl2 = (const float2*)value;
    const float2* __restrict__ tv2 = (const float2*)target_value;
    const int2*   __restrict__ st2 = (const int2*)step_type;
    const int2*   __restrict__ rb2 = (const int2*)rollout_b;
    const int2*   __restrict__ tb2 = (const int2*)train_b;
    float2*       __restrict__ ot2 = (float2*)out;

    const int base = (TD_T - 1) * P + p;
    float2 acc = __ldcs(&tv2[base]);
    __stcs(&ot2[base], make_float2(0.0f, 0.0f));

    // Double-buffered pipeline over 85 batches (odd): unroll by 2 + epilogue.
    Buf bufA, bufB;
    load_batch(bufA, 0, p, P, rw2, dc2, vl2, tv2, st2, rb2, tb2);

    #pragma unroll 1
    for (int j = 0; j + 1 < NBATCH; j += 2) {
        load_batch(bufB, j + 1, p, P, rw2, dc2, vl2, tv2, st2, rb2, tb2);
        compute_batch(bufA, j, p, P, acc, ot2);
        if (j + 2 < NBATCH)
            load_batch(bufA, j + 2, p, P, rw2, dc2, vl2, tv2, st2, rb2, tb2);
        compute_batch(bufB, j + 1, p, P, acc, ot2);
    }
    // Final batch (j = 84) already resident in bufA.
    compute_batch(bufA, NBATCH - 1, p, P, acc, ot2);
}

extern "C" void kernel_launch(void* const* d_in, const int* in_sizes, int n_in,
                              void* d_out, int out_size)
{
    const float* reward       = (const float*)d_in[0];
    const float* discount     = (const float*)d_in[1];
    const float* value        = (const float*)d_in[2];
    const float* target_value = (const float*)d_in[3];
    const int*   step_type    = (const int*)d_in[4];
    const int*   rollout_b    = (const int*)d_in[5];
    const int*   train_b      = (const int*)d_in[6];
    float*       out          = (float*)d_out;

    const int B = in_sizes[0] / TD_T;
    const int pairs = B / 2;

    const int threads = 64;
    const int blocks  = (pairs + threads - 1) / threads;
    td_loss_kernel<<<blocks, threads>>>(reward, discount, value, target_value,
                                        step_type, rollout_b, train_b, out, B);
}